// round 14
// baseline (speedup 1.0000x reference)
#include <cuda_runtime.h>

#define SEQ   512
#define BATCH 4096
#define HID   30
#define ROWP  20   // ull pairs per buf: 16 used (15 h-pairs + 1 zero pad) + 4 pad
#define PF    4    // X prefetch depth

typedef unsigned long long ull;

__device__ __forceinline__ ull pk2(float a, float b) {
    ull r; asm("mov.b64 %0,{%1,%2};" : "=l"(r) : "f"(a), "f"(b)); return r;
}
__device__ __forceinline__ void unpk2(ull v, float& a, float& b) {
    asm("mov.b64 {%0,%1},%2;" : "=f"(a), "=f"(b) : "l"(v));
}
// Packed dual-fp32 FMA / ADD (Blackwell f32x2).
__device__ __forceinline__ ull ffma2(ull a, ull b, ull c) {
    ull d; asm("fma.rn.f32x2 %0,%1,%2,%3;" : "=l"(d) : "l"(a), "l"(b), "l"(c)); return d;
}
__device__ __forceinline__ ull add2(ull a, ull b) {
    ull d; asm("add.rn.f32x2 %0,%1,%2;" : "=l"(d) : "l"(a), "l"(b)); return d;
}
// Hardware tanh (MUFU.TANH): tanh(0)==0 exactly; abs err ~1e-4 (validated: final rel_err 5.7e-6).
__device__ __forceinline__ float tanhap(float v) {
    float r; asm("tanh.approx.f32 %0, %1;" : "=f"(r) : "f"(v));
    return r;
}

__global__ void __launch_bounds__(32)
rnn_kernel(const float* __restrict__ X,     const float* __restrict__ W_ih,
           const float* __restrict__ W_hh,  const float* __restrict__ b_ih,
           const float* __restrict__ b_hh,  const float* __restrict__ W_out,
           const float* __restrict__ b_out, float* __restrict__ Y)
{
    // ONE batch per warp. h double buffer, PACKED pairs: hbuf[buf][p] = (h[2p], h[2p+1]).
    __shared__ __align__(16) ull hbuf[2][ROWP];

    const int lane = threadIdx.x;
    const int jp   = lane & 15;            // row-pair index; jp==15 -> y-row (j0) + zero pad (j1)
    const int kh   = lane >> 4;            // k-half: pairs [8kh, 8kh+8)
    const int j0   = 2 * jp, j1 = j0 + 1;
    const bool yrow = (jp == 15);
    const int batch = blockIdx.x;

    // ---- this lane's k-half of rows j0/j1, packed over (k even, k odd): 8 pairs each ----
    ull wa[8], wb[8];
#pragma unroll
    for (int i = 0; i < 8; i++) {
        const int kp = 8 * kh + i;                 // global k-pair index
        const int k0 = 2 * kp, k1 = 2 * kp + 1;
        float a0, a1;
        if (!yrow) {
            a0 = (k0 < HID) ? W_hh[j0 * HID + k0] : 0.0f;
            a1 = (k1 < HID) ? W_hh[j0 * HID + k1] : 0.0f;
        } else {
            a0 = (k0 < HID) ? W_out[k0] : 0.0f;
            a1 = (k1 < HID) ? W_out[k1] : 0.0f;
        }
        float c0 = (!yrow && k0 < HID) ? W_hh[j1 * HID + k0] : 0.0f;
        float c1 = (!yrow && k1 < HID) ? W_hh[j1 * HID + k1] : 0.0f;
        wa[i] = pk2(a0, a1);
        wb[i] = pk2(c0, c1);
    }
    // bias + x-term only on kh==0 (otherwise double-counted after the k-half combine)
    const float wih0 = (!yrow && kh == 0) ? W_ih[j0] : 0.0f;
    const float wih1 = (!yrow && kh == 0) ? W_ih[j1] : 0.0f;
    const float bi0  = (kh == 0) ? (!yrow ? (b_ih[j0] + b_hh[j0]) : b_out[0]) : 0.0f;
    const float bi1  = (!yrow && kh == 0) ? (b_ih[j1] + b_hh[j1]) : 0.0f;

    // ---- zero both buffers incl. pad ----
#pragma unroll
    for (int i = lane; i < 2 * ROWP; i += 32)
        (&hbuf[0][0])[i] = 0ull;
    __syncwarp();

    const float* Xb = X + batch;
    float*       Yb = Y + batch;

    // ---- X prefetch ring (broadcast, one line) ----
    float xbuf[PF];
#pragma unroll
    for (int i = 0; i < PF; i++) xbuf[i] = Xb[i * BATCH];

    for (int s0 = 0; s0 < SEQ; s0 += PF) {
        const float* Xpf = Xb + (s0 + PF) * BATCH;
        const bool more = (s0 + PF) < SEQ;

#pragma unroll
        for (int u = 0; u < PF; u++) {
            const int s = s0 + u;
            // static ping-pong: s&1 == u&1 (PF even)
            const ulonglong2* hc = (const ulonglong2*)&hbuf[u & 1][8 * kh]; // own k-half slice
            ull*              hn = &hbuf[(u & 1) ^ 1][0];

            const float xc = xbuf[u];
            if (more) xbuf[u] = Xpf[u * BATCH];

            // ---- partial matvec over own k-half: 4 LDS.128, 16 FFMA2, 4 chains ----
            const ulonglong2 g0 = hc[0], g1 = hc[1], g2 = hc[2], g3 = hc[3];
            ull a0 = pk2(fmaf(wih0, xc, bi0), 0.0f), a1 = 0ull;
            ull c0 = pk2(fmaf(wih1, xc, bi1), 0.0f), c1 = 0ull;
            a0 = ffma2(wa[0], g0.x, a0);  c0 = ffma2(wb[0], g0.x, c0);
            a1 = ffma2(wa[1], g0.y, a1);  c1 = ffma2(wb[1], g0.y, c1);
            a0 = ffma2(wa[2], g1.x, a0);  c0 = ffma2(wb[2], g1.x, c0);
            a1 = ffma2(wa[3], g1.y, a1);  c1 = ffma2(wb[3], g1.y, c1);
            a0 = ffma2(wa[4], g2.x, a0);  c0 = ffma2(wb[4], g2.x, c0);
            a1 = ffma2(wa[5], g2.y, a1);  c1 = ffma2(wb[5], g2.y, c1);
            a0 = ffma2(wa[6], g3.x, a0);  c0 = ffma2(wb[6], g3.x, c0);
            a1 = ffma2(wa[7], g3.y, a1);  c1 = ffma2(wb[7], g3.y, c1);

            ull sa = add2(a0, a1);
            ull sc = add2(c0, c1);

            // ---- combine k-halves: 64-bit xor-shuffle across kh (lanes jp <-> jp+16) ----
            const ull sap = __shfl_xor_sync(0xffffffffu, sa, 16);
            const ull scp = __shfl_xor_sync(0xffffffffu, sc, 16);
            sa = add2(sa, sap);            // bitwise-identical in both halves (fadd commutes)
            sc = add2(sc, scp);

            float sa0, sa1, sc0, sc1;
            unpk2(sa, sa0, sa1);
            unpk2(sc, sc0, sc1);
            const float v0 = sa0 + sa1;    // jp<15: pre-tanh j0 ; jp==15: y[s-1]
            const float v1 = sc0 + sc1;

            // ---- y store (lane 15 only, predicated — warp stays convergent) ----
            if (lane == 15 && s > 0) Yb[(s - 1) * BATCH] = v0;

            // ---- tanh + publish packed pair (STS.64 from kh==0 lanes) ----
            const float h0 = tanhap(v0);
            const float h1 = tanhap(v1);   // jp==15: v1==0 -> h1==0 exactly
            if (kh == 0) hn[jp] = pk2(yrow ? 0.0f : h0, h1);

            // compiler barrier: keep next step's LDS after this STS (same-warp MIO in-order)
            asm volatile("" ::: "memory");
        }
    }

    // ---- epilogue: y[SEQ-1] from final state (buffer 0, SEQ even) ----
    {
        const ulonglong2* hc = (const ulonglong2*)&hbuf[0][8 * kh];
        const ulonglong2 g0 = hc[0], g1 = hc[1], g2 = hc[2], g3 = hc[3];
        ull a0 = pk2(bi0, 0.0f), a1 = 0ull;
        a0 = ffma2(wa[0], g0.x, a0);  a1 = ffma2(wa[1], g0.y, a1);
        a0 = ffma2(wa[2], g1.x, a0);  a1 = ffma2(wa[3], g1.y, a1);
        a0 = ffma2(wa[4], g2.x, a0);  a1 = ffma2(wa[5], g2.y, a1);
        a0 = ffma2(wa[6], g3.x, a0);  a1 = ffma2(wa[7], g3.y, a1);
        ull sa = add2(a0, a1);
        const ull sap = __shfl_xor_sync(0xffffffffu, sa, 16);
        sa = add2(sa, sap);
        float s0v, s1v;
        unpk2(sa, s0v, s1v);
        if (lane == 15) Yb[(SEQ - 1) * BATCH] = s0v + s1v;
    }
}

extern "C" void kernel_launch(void* const* d_in, const int* in_sizes, int n_in,
                              void* d_out, int out_size)
{
    (void)in_sizes; (void)n_in; (void)out_size;
    rnn_kernel<<<BATCH, 32>>>(
        (const float*)d_in[0],  // X
        (const float*)d_in[1],  // W_ih
        (const float*)d_in[2],  // W_hh
        (const float*)d_in[3],  // b_ih
        (const float*)d_in[4],  // b_hh
        (const float*)d_in[5],  // W_out
        (const float*)d_in[6],  // b_out
        (float*)d_out);
}

// round 15
// speedup vs baseline: 1.2136x; 1.2136x over previous
#include <cuda_runtime.h>

#define SEQ   512
#define BATCH 4096
#define HID   30
#define ROWP  24   // ull pairs per (buf,b) row: 16 loaded (15 h-pairs + 1 zero pad) + 8 pad
#define PF    8    // X prefetch depth

typedef unsigned long long ull;

__device__ __forceinline__ ull pk2(float a, float b) {
    ull r; asm("mov.b64 %0,{%1,%2};" : "=l"(r) : "f"(a), "f"(b)); return r;
}
__device__ __forceinline__ void unpk2(ull v, float& a, float& b) {
    asm("mov.b64 {%0,%1},%2;" : "=f"(a), "=f"(b) : "l"(v));
}
// Packed dual-fp32 FMA / ADD (Blackwell f32x2).
__device__ __forceinline__ ull ffma2(ull a, ull b, ull c) {
    ull d; asm("fma.rn.f32x2 %0,%1,%2,%3;" : "=l"(d) : "l"(a), "l"(b), "l"(c)); return d;
}
__device__ __forceinline__ ull add2(ull a, ull b) {
    ull d; asm("add.rn.f32x2 %0,%1,%2;" : "=l"(d) : "l"(a), "l"(b)); return d;
}
// Hardware tanh (MUFU.TANH): tanh(0)==0 exactly; validated rel_err 5.7e-6 end-to-end.
__device__ __forceinline__ float tanhap(float v) {
    float r; asm("tanh.approx.f32 %0, %1;" : "=f"(r) : "f"(v));
    return r;
}

__global__ void __launch_bounds__(32)
rnn_kernel(const float* __restrict__ X,     const float* __restrict__ W_ih,
           const float* __restrict__ W_hh,  const float* __restrict__ b_ih,
           const float* __restrict__ b_hh,  const float* __restrict__ W_out,
           const float* __restrict__ b_out, float* __restrict__ Y)
{
    // h double buffer, PACKED pairs: hbuf[buf][b][p] = (h[2p], h[2p+1]); p=15 zero pad.
    __shared__ __align__(16) ull hbuf[2][2][ROWP];

    const int lane = threadIdx.x;
    const int jp   = lane & 15;            // row-pair index; jp==15 -> y-row (j0) + zero pad (j1)
    const int b    = lane >> 4;            // SIMT batch half
    const int j0   = 2 * jp, j1 = j0 + 1;
    const bool yrow = (jp == 15);
    const int batch = blockIdx.x * 2 + b;

    // ---- weights packed over (k even, k odd): wa = row j0, wb = row j1 ----
    // jp<15: W_hh rows; jp==15: wa = W_out, wb = 0 (free output projection).
    ull wa[16], wb[16];
#pragma unroll
    for (int i = 0; i < 16; i++) {
        const int k0 = 2 * i, k1 = 2 * i + 1;
        float a0, a1;
        if (!yrow) {
            a0 = (k0 < HID) ? W_hh[j0 * HID + k0] : 0.0f;
            a1 = (k1 < HID) ? W_hh[j0 * HID + k1] : 0.0f;
        } else {
            a0 = (k0 < HID) ? W_out[k0] : 0.0f;
            a1 = (k1 < HID) ? W_out[k1] : 0.0f;
        }
        float c0 = (!yrow && k0 < HID) ? W_hh[j1 * HID + k0] : 0.0f;
        float c1 = (!yrow && k1 < HID) ? W_hh[j1 * HID + k1] : 0.0f;
        wa[i] = pk2(a0, a1);
        wb[i] = pk2(c0, c1);
    }
    const float wih0 = !yrow ? W_ih[j0] : 0.0f;
    const float wih1 = !yrow ? W_ih[j1] : 0.0f;
    const float bi0  = !yrow ? (b_ih[j0] + b_hh[j0]) : b_out[0];
    const float bi1  = !yrow ? (b_ih[j1] + b_hh[j1]) : 0.0f;

    // ---- zero both buffers incl. pad ----
#pragma unroll
    for (int i = lane; i < 2 * 2 * ROWP; i += 32)
        (&hbuf[0][0][0])[i] = 0ull;
    __syncwarp();

    const float* Xb = X + batch;
    float*       Yb = Y + batch;

    // ---- X prefetch ring ----
    float xbuf[PF];
#pragma unroll
    for (int i = 0; i < PF; i++) xbuf[i] = Xb[i * BATCH];

    for (int s0 = 0; s0 < SEQ; s0 += PF) {
        const float* Xpf = Xb + (s0 + PF) * BATCH;
        const bool more = (s0 + PF) < SEQ;

#pragma unroll
        for (int u = 0; u < PF; u++) {
            const int s = s0 + u;
            // static ping-pong: s&1 == u&1 (PF even, s0 multiple of PF)
            const ulonglong2* hc = (const ulonglong2*)&hbuf[u & 1][b][0];
            ull*              hn = &hbuf[(u & 1) ^ 1][b][0];

            const float xc = xbuf[u];
            if (more) xbuf[u] = Xpf[u * BATCH];

            // ---- matvec rows j0,j1: 16 k-pairs, 2 chains/row (depth 8), 8 LDS.128.
            //      Chain element order puts the last-arriving load (g7) at chain ends. ----
            const ulonglong2 g0 = hc[0], g1 = hc[1], g2 = hc[2], g3 = hc[3];
            const ulonglong2 g4 = hc[4], g5 = hc[5], g6 = hc[6], g7 = hc[7];
            ull a0 = pk2(fmaf(wih0, xc, bi0), 0.0f), a1 = 0ull;   // row j0 (even/odd k-pairs)
            ull c0 = pk2(fmaf(wih1, xc, bi1), 0.0f), c1 = 0ull;   // row j1
            a0 = ffma2(wa[0],  g0.x, a0);  c0 = ffma2(wb[0],  g0.x, c0);
            a1 = ffma2(wa[1],  g0.y, a1);  c1 = ffma2(wb[1],  g0.y, c1);
            a0 = ffma2(wa[2],  g1.x, a0);  c0 = ffma2(wb[2],  g1.x, c0);
            a1 = ffma2(wa[3],  g1.y, a1);  c1 = ffma2(wb[3],  g1.y, c1);
            a0 = ffma2(wa[4],  g2.x, a0);  c0 = ffma2(wb[4],  g2.x, c0);
            a1 = ffma2(wa[5],  g2.y, a1);  c1 = ffma2(wb[5],  g2.y, c1);
            a0 = ffma2(wa[6],  g3.x, a0);  c0 = ffma2(wb[6],  g3.x, c0);
            a1 = ffma2(wa[7],  g3.y, a1);  c1 = ffma2(wb[7],  g3.y, c1);
            a0 = ffma2(wa[8],  g4.x, a0);  c0 = ffma2(wb[8],  g4.x, c0);
            a1 = ffma2(wa[9],  g4.y, a1);  c1 = ffma2(wb[9],  g4.y, c1);
            a0 = ffma2(wa[10], g5.x, a0);  c0 = ffma2(wb[10], g5.x, c0);
            a1 = ffma2(wa[11], g5.y, a1);  c1 = ffma2(wb[11], g5.y, c1);
            a0 = ffma2(wa[12], g6.x, a0);  c0 = ffma2(wb[12], g6.x, c0);
            a1 = ffma2(wa[13], g6.y, a1);  c1 = ffma2(wb[13], g6.y, c1);
            a0 = ffma2(wa[14], g7.x, a0);  c0 = ffma2(wb[14], g7.x, c0);
            a1 = ffma2(wa[15], g7.y, a1);  c1 = ffma2(wb[15], g7.y, c1);

            const ull sa = add2(a0, a1);   // single combine per row
            const ull sc = add2(c0, c1);
            float sa0, sa1, sc0, sc1;
            unpk2(sa, sa0, sa1);
            unpk2(sc, sc0, sc1);
            const float v0 = sa0 + sa1;    // jp<15: pre-tanh j0 ; jp==15: y[s-1]
            const float v1 = sc0 + sc1;

            // ---- y store (lanes 15/31, predicated — warp stays convergent) ----
            if (yrow && s > 0) Yb[(s - 1) * BATCH] = v0;

            // ---- tanh (1 MUFU op each) + publish packed pair (STS.64) ----
            const float h0 = tanhap(v0);
            const float h1 = tanhap(v1);   // jp==15: v1==0 -> h1==0 exactly
            hn[jp] = pk2(yrow ? 0.0f : h0, h1);

            // compiler barrier: keep next step's LDS after this STS (same-warp MIO in-order)
            asm volatile("" ::: "memory");
        }
    }

    // ---- epilogue: y[SEQ-1] from final state (buffer 0, SEQ even) ----
    {
        const ulonglong2* hc = (const ulonglong2*)&hbuf[0][b][0];
        ull a0 = pk2(bi0, 0.0f), a1 = 0ull;
#pragma unroll
        for (int i = 0; i < 8; i++) {
            const ulonglong2 g = hc[i];
            a0 = ffma2(wa[2 * i],     g.x, a0);
            a1 = ffma2(wa[2 * i + 1], g.y, a1);
        }
        const ull sa = add2(a0, a1);
        float s0v, s1v;
        unpk2(sa, s0v, s1v);
        if (yrow) Yb[(SEQ - 1) * BATCH] = s0v + s1v;
    }
}

extern "C" void kernel_launch(void* const* d_in, const int* in_sizes, int n_in,
                              void* d_out, int out_size)
{
    (void)in_sizes; (void)n_in; (void)out_size;
    rnn_kernel<<<BATCH / 2, 32>>>(
        (const float*)d_in[0],  // X
        (const float*)d_in[1],  // W_ih
        (const float*)d_in[2],  // W_hh
        (const float*)d_in[3],  // b_ih
        (const float*)d_in[4],  // b_hh
        (const float*)d_in[5],  // W_out
        (const float*)d_in[6],  // b_out
        (float*)d_out);
}

// round 16
// speedup vs baseline: 1.2523x; 1.0319x over previous
#include <cuda_runtime.h>

#define SEQ   512
#define BATCH 4096
#define HID   30
#define ROWP  24   // ull pairs per (buf,b) row: 15 used + pad (layout/alignment preserved)
#define PF    8    // X prefetch depth

typedef unsigned long long ull;

__device__ __forceinline__ ull pk2(float a, float b) {
    ull r; asm("mov.b64 %0,{%1,%2};" : "=l"(r) : "f"(a), "f"(b)); return r;
}
__device__ __forceinline__ void unpk2(ull v, float& a, float& b) {
    asm("mov.b64 {%0,%1},%2;" : "=f"(a), "=f"(b) : "l"(v));
}
// Packed dual-fp32 FMA / ADD (Blackwell f32x2).
__device__ __forceinline__ ull ffma2(ull a, ull b, ull c) {
    ull d; asm("fma.rn.f32x2 %0,%1,%2,%3;" : "=l"(d) : "l"(a), "l"(b), "l"(c)); return d;
}
__device__ __forceinline__ ull add2(ull a, ull b) {
    ull d; asm("add.rn.f32x2 %0,%1,%2;" : "=l"(d) : "l"(a), "l"(b)); return d;
}
// Hardware tanh (MUFU.TANH): tanh(0)==0 exactly; validated rel_err 5.7e-6 end-to-end.
__device__ __forceinline__ float tanhap(float v) {
    float r; asm("tanh.approx.f32 %0, %1;" : "=f"(r) : "f"(v));
    return r;
}

__global__ void __launch_bounds__(32)
rnn_kernel(const float* __restrict__ X,     const float* __restrict__ W_ih,
           const float* __restrict__ W_hh,  const float* __restrict__ b_ih,
           const float* __restrict__ b_hh,  const float* __restrict__ W_out,
           const float* __restrict__ b_out, float* __restrict__ Y)
{
    // h double buffer, PACKED pairs: hbuf[buf][b][p] = (h[2p], h[2p+1]), p = 0..14.
    __shared__ __align__(16) ull hbuf[2][2][ROWP];

    const int lane = threadIdx.x;
    const int jp   = lane & 15;            // row-pair index; jp==15 -> y-row (j0), j1 unused
    const int b    = lane >> 4;            // SIMT batch half
    const int j0   = 2 * jp, j1 = j0 + 1;
    const bool yrow = (jp == 15);
    const int batch = blockIdx.x * 2 + b;

    // ---- weights packed over (k even, k odd), 15 pairs: wa = row j0, wb = row j1 ----
    // jp<15: W_hh rows; jp==15: wa = W_out, wb = 0 (free output projection).
    ull wa[15], wb[15];
#pragma unroll
    for (int i = 0; i < 15; i++) {
        const int k0 = 2 * i, k1 = 2 * i + 1;
        float a0, a1;
        if (!yrow) {
            a0 = W_hh[j0 * HID + k0];
            a1 = W_hh[j0 * HID + k1];
        } else {
            a0 = W_out[k0];
            a1 = W_out[k1];
        }
        float c0 = !yrow ? W_hh[j1 * HID + k0] : 0.0f;
        float c1 = !yrow ? W_hh[j1 * HID + k1] : 0.0f;
        wa[i] = pk2(a0, a1);
        wb[i] = pk2(c0, c1);
    }
    const float wih0 = !yrow ? W_ih[j0] : 0.0f;
    const float wih1 = !yrow ? W_ih[j1] : 0.0f;
    const float bi0  = !yrow ? (b_ih[j0] + b_hh[j0]) : b_out[0];
    const float bi1  = !yrow ? (b_ih[j1] + b_hh[j1]) : 0.0f;
    const ull  bias0 = pk2(bi0, 0.0f);     // constant chain-head inits (hoisted out of loop)
    const ull  bias1 = pk2(bi1, 0.0f);

    // ---- zero both buffers incl. pad ----
#pragma unroll
    for (int i = lane; i < 2 * 2 * ROWP; i += 32)
        (&hbuf[0][0][0])[i] = 0ull;
    __syncwarp();

    const float* Xb = X + batch;
    float*       Yb = Y + batch;

    // ---- X prefetch ring ----
    float xbuf[PF];
#pragma unroll
    for (int i = 0; i < PF; i++) xbuf[i] = Xb[i * BATCH];

    for (int s0 = 0; s0 < SEQ; s0 += PF) {
        const float* Xpf = Xb + (s0 + PF) * BATCH;
        const bool more = (s0 + PF) < SEQ;

#pragma unroll
        for (int u = 0; u < PF; u++) {
            const int s = s0 + u;
            // static ping-pong: s&1 == u&1 (PF even, s0 multiple of PF)
            const ulonglong2* hc = (const ulonglong2*)&hbuf[u & 1][b][0];
            ull*              hn = &hbuf[(u & 1) ^ 1][b][0];

            const float xc = xbuf[u];
            if (more) xbuf[u] = Xpf[u * BATCH];

            // ---- matvec rows j0,j1: 15 k-pairs, 2 chains/row, 7 LDS.128 + 1 LDS.64.
            //      Bias-const chain heads; x-term applied at the tail (LDG off the path). ----
            const ulonglong2 g0 = hc[0], g1 = hc[1], g2 = hc[2], g3 = hc[3];
            const ulonglong2 g4 = hc[4], g5 = hc[5], g6 = hc[6];
            const ull        g7 = *(const ull*)&hc[7];   // pair 14 (h28, h29)
            ull a0 = bias0, a1 = 0ull;     // row j0: even / odd k-pairs
            ull c0 = bias1, c1 = 0ull;     // row j1
            a0 = ffma2(wa[0],  g0.x, a0);  c0 = ffma2(wb[0],  g0.x, c0);
            a1 = ffma2(wa[1],  g0.y, a1);  c1 = ffma2(wb[1],  g0.y, c1);
            a0 = ffma2(wa[2],  g1.x, a0);  c0 = ffma2(wb[2],  g1.x, c0);
            a1 = ffma2(wa[3],  g1.y, a1);  c1 = ffma2(wb[3],  g1.y, c1);
            a0 = ffma2(wa[4],  g2.x, a0);  c0 = ffma2(wb[4],  g2.x, c0);
            a1 = ffma2(wa[5],  g2.y, a1);  c1 = ffma2(wb[5],  g2.y, c1);
            a0 = ffma2(wa[6],  g3.x, a0);  c0 = ffma2(wb[6],  g3.x, c0);
            a1 = ffma2(wa[7],  g3.y, a1);  c1 = ffma2(wb[7],  g3.y, c1);
            a0 = ffma2(wa[8],  g4.x, a0);  c0 = ffma2(wb[8],  g4.x, c0);
            a1 = ffma2(wa[9],  g4.y, a1);  c1 = ffma2(wb[9],  g4.y, c1);
            a0 = ffma2(wa[10], g5.x, a0);  c0 = ffma2(wb[10], g5.x, c0);
            a1 = ffma2(wa[11], g5.y, a1);  c1 = ffma2(wb[11], g5.y, c1);
            a0 = ffma2(wa[12], g6.x, a0);  c0 = ffma2(wb[12], g6.x, c0);
            a1 = ffma2(wa[13], g6.y, a1);  c1 = ffma2(wb[13], g6.y, c1);
            a0 = ffma2(wa[14], g7,   a0);  c0 = ffma2(wb[14], g7,   c0);

            const ull sa = add2(a0, a1);
            const ull sc = add2(c0, c1);
            float sa0, sa1, sc0, sc1;
            unpk2(sa, sa0, sa1);
            unpk2(sc, sc0, sc1);
            const float v0 = fmaf(wih0, xc, sa0 + sa1);  // jp<15: pre-tanh j0 ; jp==15: y[s-1]
            const float v1 = fmaf(wih1, xc, sc0 + sc1);

            // ---- y store (lanes 15/31, predicated — warp stays convergent) ----
            if (yrow && s > 0) Yb[(s - 1) * BATCH] = v0;

            // ---- tanh + publish packed pair (STS.64, jp<15 only; pad never read) ----
            const float h0 = tanhap(v0);
            const float h1 = tanhap(v1);
            if (!yrow) hn[jp] = pk2(h0, h1);

            // compiler barrier: keep next step's LDS after this STS (same-warp MIO in-order)
            asm volatile("" ::: "memory");
        }
    }

    // ---- epilogue: y[SEQ-1] from final state (buffer 0, SEQ even) ----
    {
        const ulonglong2* hc = (const ulonglong2*)&hbuf[0][b][0];
        ull a0 = bias0, a1 = 0ull;
#pragma unroll
        for (int i = 0; i < 7; i++) {
            const ulonglong2 g = hc[i];
            a0 = ffma2(wa[2 * i],     g.x, a0);
            a1 = ffma2(wa[2 * i + 1], g.y, a1);
        }
        a0 = ffma2(wa[14], *(const ull*)&hc[7], a0);
        const ull sa = add2(a0, a1);
        float s0v, s1v;
        unpk2(sa, s0v, s1v);
        if (yrow) Yb[(SEQ - 1) * BATCH] = s0v + s1v;
    }
}

extern "C" void kernel_launch(void* const* d_in, const int* in_sizes, int n_in,
                              void* d_out, int out_size)
{
    (void)in_sizes; (void)n_in; (void)out_size;
    rnn_kernel<<<BATCH / 2, 32>>>(
        (const float*)d_in[0],  // X
        (const float*)d_in[1],  // W_ih
        (const float*)d_in[2],  // W_hh
        (const float*)d_in[3],  // b_ih
        (const float*)d_in[4],  // b_hh
        (const float*)d_in[5],  // W_out
        (const float*)d_in[6],  // b_out
        (float*)d_out);
}